// round 5
// baseline (speedup 1.0000x reference)
#include <cuda_runtime.h>
#include <cuda_bf16.h>
#include <math.h>
#include <stdint.h>

#define BATCH 4
#define SEQ   2048
#define HIDN  512
#define NH    8
#define HD    64
#define SWIN  250
#define MTOT  (BATCH*SEQ)            // 8192
#define MATSZ (BATCH*NH*SEQ*HD)      // 4.19M elements per Q/K/V matrix

// ---------------- device-global scratch ------------------------------------
__device__ __nv_bfloat16 g_Xh[MTOT*HIDN], g_Xl[MTOT*HIDN];
__device__ __nv_bfloat16 g_Wh[3*HIDN*HIDN], g_Wl[3*HIDN*HIDN];  // Wq(.125)|Wk|Wv
__device__ __nv_bfloat16 g_Ah[MTOT*HIDN], g_Al[MTOT*HIDN];      // attn out, split
__device__ __nv_bfloat16 g_Woh[HIDN*HIDN], g_Wol[HIDN*HIDN];
__device__ __nv_bfloat16 g_Qh[MATSZ], g_Ql[MATSZ];   // RoPE'd, prescaled 1/8
__device__ __nv_bfloat16 g_Kh[MATSZ], g_Kl[MATSZ];   // RoPE'd
__device__ __nv_bfloat16 g_Vh[MATSZ], g_Vl[MATSZ];
__device__ float2 g_rope[SEQ*32];              // cos,sin per (pos, freq)

// ---------------- PTX helpers ----------------------------------------------
__device__ __forceinline__ uint32_t smem_u32(const void* p) {
    uint32_t a;
    asm("{ .reg .u64 t; cvta.to.shared.u64 t, %1; cvt.u32.u64 %0, t; }"
        : "=r"(a) : "l"(p));
    return a;
}
__device__ __forceinline__ void cp16(uint32_t d, const void* s) {
    asm volatile("cp.async.cg.shared.global [%0], [%1], 16;"
                 :: "r"(d), "l"(__cvta_generic_to_global(s)) : "memory");
}
#define CP_COMMIT() asm volatile("cp.async.commit_group;" ::: "memory")
#define CP_WAIT1()  asm volatile("cp.async.wait_group 1;" ::: "memory")

__device__ __forceinline__ void ldm4(uint32_t* r, uint32_t addr) {
    asm volatile("ldmatrix.sync.aligned.m8n8.x4.shared.b16 {%0,%1,%2,%3}, [%4];"
        : "=r"(r[0]), "=r"(r[1]), "=r"(r[2]), "=r"(r[3]) : "r"(addr));
}
__device__ __forceinline__ void ldm4t(uint32_t* r, uint32_t addr) {
    asm volatile("ldmatrix.sync.aligned.m8n8.x4.trans.shared.b16 {%0,%1,%2,%3}, [%4];"
        : "=r"(r[0]), "=r"(r[1]), "=r"(r[2]), "=r"(r[3]) : "r"(addr));
}
__device__ __forceinline__ void mma_bf16(float* d, const uint32_t* a,
                                         uint32_t b0, uint32_t b1) {
    asm volatile("mma.sync.aligned.m16n8k16.row.col.f32.bf16.bf16.f32 "
        "{%0,%1,%2,%3}, {%4,%5,%6,%7}, {%8,%9}, {%0,%1,%2,%3};"
        : "+f"(d[0]), "+f"(d[1]), "+f"(d[2]), "+f"(d[3])
        : "r"(a[0]), "r"(a[1]), "r"(a[2]), "r"(a[3]), "r"(b0), "r"(b1));
}

__device__ __forceinline__ void store_split(__nv_bfloat16* hp, __nv_bfloat16* lp,
                                            size_t idx, float x, float y) {
    __nv_bfloat16 hx = __float2bfloat16(x), hy = __float2bfloat16(y);
    __nv_bfloat16 lx = __float2bfloat16(x - __bfloat162float(hx));
    __nv_bfloat16 ly = __float2bfloat16(y - __bfloat162float(hy));
    *(__nv_bfloat162*)(hp + idx) = __halves2bfloat162(hx, hy);
    *(__nv_bfloat162*)(lp + idx) = __halves2bfloat162(lx, ly);
}

// ---------------- conversion kernels ---------------------------------------
// which: 0 = X -> g_Xh/g_Xl, 2 = Wo -> g_Woh/g_Wol
__global__ void cvt_in(const float* __restrict__ s, int n4, float scale, int which)
{
    int i = blockIdx.x * 256 + threadIdx.x;
    if (i >= n4) return;
    __nv_bfloat16 *hp, *lp;
    if (which == 0) { hp = g_Xh;  lp = g_Xl;  }
    else            { hp = g_Woh; lp = g_Wol; }
    float4 v = ((const float4*)s)[i];
    float x[4] = { v.x * scale, v.y * scale, v.z * scale, v.w * scale };
    __nv_bfloat16 h[4], l[4];
    #pragma unroll
    for (int j = 0; j < 4; j++) {
        h[j] = __float2bfloat16(x[j]);
        l[j] = __float2bfloat16(x[j] - __bfloat162float(h[j]));
    }
    ((__nv_bfloat162*)hp)[2*i]   = __halves2bfloat162(h[0], h[1]);
    ((__nv_bfloat162*)hp)[2*i+1] = __halves2bfloat162(h[2], h[3]);
    ((__nv_bfloat162*)lp)[2*i]   = __halves2bfloat162(l[0], l[1]);
    ((__nv_bfloat162*)lp)[2*i+1] = __halves2bfloat162(l[2], l[3]);
}

// Wq/Wk/Wv in one launch: blockIdx.y picks the matrix
__global__ void cvt_w(const float* __restrict__ Wq, const float* __restrict__ Wk,
                      const float* __restrict__ Wv)
{
    int y = blockIdx.y;
    const float* s = (y == 0) ? Wq : (y == 1) ? Wk : Wv;
    float scale = (y == 0) ? 0.125f : 1.0f;
    __nv_bfloat16* hp = g_Wh + (size_t)y * HIDN * HIDN;
    __nv_bfloat16* lp = g_Wl + (size_t)y * HIDN * HIDN;
    int i = blockIdx.x * 256 + threadIdx.x;          // n4 = 65536
    float4 v = ((const float4*)s)[i];
    float x[4] = { v.x * scale, v.y * scale, v.z * scale, v.w * scale };
    __nv_bfloat16 h[4], l[4];
    #pragma unroll
    for (int j = 0; j < 4; j++) {
        h[j] = __float2bfloat16(x[j]);
        l[j] = __float2bfloat16(x[j] - __bfloat162float(h[j]));
    }
    ((__nv_bfloat162*)hp)[2*i]   = __halves2bfloat162(h[0], h[1]);
    ((__nv_bfloat162*)hp)[2*i+1] = __halves2bfloat162(h[2], h[3]);
    ((__nv_bfloat162*)lp)[2*i]   = __halves2bfloat162(l[0], l[1]);
    ((__nv_bfloat162*)lp)[2*i+1] = __halves2bfloat162(l[2], l[3]);
}

__global__ void rope_tab()
{
    int pos = blockIdx.x, j = threadIdx.x;           // 2048 x 32
    double li = 9.210340371976184 / 32.0;            // ln(10000)/32
    float invf = (float)exp(-(double)j * li);
    float sn, cs;
    sincosf((float)pos * invf, &sn, &cs);
    g_rope[pos * 32 + j] = make_float2(cs, sn);
}

// ---------------- mma.sync GEMM, bf16 3-pass split -------------------------
// C[m,n] = sum_k A[m,k]*B[n,k];  tiles 128x128, K-chunk 32, 8 warps (4m x 2n)
#define TILE_B   10240
#define STAGE_B  40960
#define GSMEM_BYTES (2*STAGE_B)

__global__ __launch_bounds__(256, 1) void gemm_mma(float* __restrict__ outp, int mode)
{
    extern __shared__ char smem[];
    uint32_t sb = smem_u32(smem);
    int tid = threadIdx.x, lane = tid & 31, warp = tid >> 5;
    int mw = warp & 3, nw = warp >> 2;
    int m0 = blockIdx.x * 128;
    int y  = blockIdx.y;
    int n0g = y * 128;

    const __nv_bfloat16 *Agh, *Agl, *Bgh, *Bgl;
    if (mode == 0) { Agh = g_Xh; Agl = g_Xl; Bgh = g_Wh;  Bgl = g_Wl;  }
    else           { Agh = g_Ah; Agl = g_Al; Bgh = g_Woh; Bgl = g_Wol; }

    int lrow = tid >> 2, lq = tid & 3;
    const __nv_bfloat16* pAh = Agh + (size_t)(m0 + lrow) * HIDN + lq * 8;
    const __nv_bfloat16* pAl = Agl + (size_t)(m0 + lrow) * HIDN + lq * 8;
    const __nv_bfloat16* pBh = Bgh + (size_t)(n0g + lrow) * HIDN + lq * 8;
    const __nv_bfloat16* pBl = Bgl + (size_t)(n0g + lrow) * HIDN + lq * 8;
    uint32_t sdst = sb + lrow * 80 + lq * 16;

#define LDST(st, c) do {                                                       \
    int _k = (c) * 32;                                                         \
    uint32_t _d = sdst + (st) * STAGE_B;                                       \
    cp16(_d,                     pAh + _k); cp16(_d + 64*80,             pAh + _k + 64*HIDN); \
    cp16(_d + TILE_B,            pAl + _k); cp16(_d + TILE_B + 64*80,    pAl + _k + 64*HIDN); \
    cp16(_d + 2*TILE_B,          pBh + _k); cp16(_d + 2*TILE_B + 64*80,  pBh + _k + 64*HIDN); \
    cp16(_d + 3*TILE_B,          pBl + _k); cp16(_d + 3*TILE_B + 64*80,  pBl + _k + 64*HIDN); \
} while (0)

    float acc[2][8][4];
    #pragma unroll
    for (int a = 0; a < 2; a++)
        #pragma unroll
        for (int bq = 0; bq < 8; bq++)
            #pragma unroll
            for (int c = 0; c < 4; c++) acc[a][bq][c] = 0.f;

    uint32_t aaddr0 = sb + (mw * 32 + (lane & 15)) * 80 + (lane >> 4) * 16;
    uint32_t baddr0 = sb + 2 * TILE_B + (nw * 64 + (lane & 15)) * 80 + (lane >> 4) * 16;

    LDST(0, 0);
    CP_COMMIT();

    for (int c = 0; c < 16; c++) {
        if (c + 1 < 16) LDST((c + 1) & 1, c + 1);
        CP_COMMIT();
        CP_WAIT1();
        __syncthreads();
        uint32_t sa = aaddr0 + (c & 1) * STAGE_B;
        uint32_t sbb = baddr0 + (c & 1) * STAGE_B;
        #pragma unroll
        for (int ks = 0; ks < 2; ks++) {
            uint32_t ka = sa + ks * 32, kb = sbb + ks * 32;
            uint32_t ah[2][4], al[2][4], bh[4][4], bl[4][4];
            ldm4(ah[0], ka);          ldm4(ah[1], ka + 1280);
            ldm4(al[0], ka + TILE_B); ldm4(al[1], ka + TILE_B + 1280);
            #pragma unroll
            for (int j = 0; j < 4; j++) {
                ldm4(bh[j], kb + j * 1280);
                ldm4(bl[j], kb + TILE_B + j * 1280);
            }
            #pragma unroll
            for (int mi = 0; mi < 2; mi++)
                #pragma unroll
                for (int j = 0; j < 4; j++) {
                    mma_bf16(acc[mi][2*j],   ah[mi], bh[j][0], bh[j][2]);
                    mma_bf16(acc[mi][2*j+1], ah[mi], bh[j][1], bh[j][3]);
                    mma_bf16(acc[mi][2*j],   al[mi], bh[j][0], bh[j][2]);
                    mma_bf16(acc[mi][2*j+1], al[mi], bh[j][1], bh[j][3]);
                    mma_bf16(acc[mi][2*j],   ah[mi], bl[j][0], bl[j][2]);
                    mma_bf16(acc[mi][2*j+1], ah[mi], bl[j][1], bl[j][3]);
                }
        }
        __syncthreads();
    }

    if (mode == 0) {
        int mat = y >> 2;                       // 0=Q,1=K,2=V
        int h   = ((y & 3) << 1) + nw;          // head
        __nv_bfloat16 *hp, *lp;
        if (mat == 0)      { hp = g_Qh; lp = g_Ql; }
        else if (mat == 1) { hp = g_Kh; lp = g_Kl; }
        else               { hp = g_Vh; lp = g_Vl; }
        #pragma unroll
        for (int mi = 0; mi < 2; mi++)
            #pragma unroll
            for (int half = 0; half < 2; half++) {
                int m = m0 + mw * 32 + mi * 16 + (lane >> 2) + half * 8;
                int bb = m >> 11, spos = m & (SEQ - 1);
                size_t base = ((size_t)(bb * NH + h) * SEQ + spos) * HD;
                int dlo = 2 * (lane & 3);
                if (mat == 2) {
                    #pragma unroll
                    for (int p = 0; p < 8; p++)
                        store_split(hp, lp, base + p * 8 + dlo,
                                    acc[mi][p][2*half], acc[mi][p][2*half+1]);
                } else {
                    #pragma unroll
                    for (int p = 0; p < 4; p++) {
                        int d = p * 8 + dlo;
                        float4 t = *(const float4*)&g_rope[spos * 32 + d]; // cs0,sn0,cs1,sn1
                        float a0 = acc[mi][p][2*half],   a1 = acc[mi][p][2*half+1];
                        float b0 = acc[mi][p+4][2*half], b1 = acc[mi][p+4][2*half+1];
                        store_split(hp, lp, base + d,      a0*t.x - b0*t.y, a1*t.z - b1*t.w);
                        store_split(hp, lp, base + d + 32, b0*t.x + a0*t.y, b1*t.z + a1*t.w);
                    }
                }
            }
    } else {
        #pragma unroll
        for (int mi = 0; mi < 2; mi++)
            #pragma unroll
            for (int half = 0; half < 2; half++) {
                int m = m0 + mw * 32 + mi * 16 + (lane >> 2) + half * 8;
                float* dst = outp + (size_t)m * HIDN + n0g + nw * 64 + 2 * (lane & 3);
                #pragma unroll
                for (int p = 0; p < 8; p++)
                    *(float2*)&dst[p * 8] =
                        make_float2(acc[mi][p][2*half], acc[mi][p][2*half+1]);
            }
    }
}

// ---------------- flash attention via mma.sync bf16-split ------------------
// Block = 128 q rows, 8 warps (16 rows each), k-tile 64, 2-stage cp.async.
// smem rows padded to 144 B for conflict-free ldmatrix.
#define AST     144
#define QT_B    (128*AST)                       // 18432 per Q tile (hi or lo)
#define KT_B    (64*AST)                        // 9216 per K/V tile
#define ATTN_SMEM (2*QT_B + 2*4*KT_B)           // 110592

__global__ __launch_bounds__(256) void attn_mma()
{
    extern __shared__ char smem[];
    uint32_t sb = smem_u32(smem);
    int tid = threadIdx.x, lane = tid & 31, warp = tid >> 5;
    int qt = blockIdx.x, h = blockIdx.y, b = blockIdx.z;
    int q0 = qt * 128;
    size_t hoff = (size_t)(b * NH + h) * SEQ * HD;
    const __nv_bfloat16 *Qhg = g_Qh + hoff + (size_t)q0 * HD;
    const __nv_bfloat16 *Qlg = g_Ql + hoff + (size_t)q0 * HD;
    const __nv_bfloat16 *Khg = g_Kh + hoff, *Klg = g_Kl + hoff;
    const __nv_bfloat16 *Vhg = g_Vh + hoff, *Vlg = g_Vl + hoff;

    // prologue: Q tiles (hi, lo): 128 rows x 8 chunks x 2 = 2048 cp16
    #pragma unroll
    for (int p = 0; p < 4; p++) {
        int i = tid + p * 256;
        int row = i >> 3, c = i & 7;
        uint32_t off = (uint32_t)(row * AST + c * 16);
        const int so = row * HD + c * 8;
        cp16(sb + off,        Qhg + so);
        cp16(sb + QT_B + off, Qlg + so);
    }

#define LOADKV(st, kb) do {                                                    \
    uint32_t _bs = sb + 2*QT_B + (st) * 4*KT_B;                                \
    _Pragma("unroll")                                                          \
    for (int p = 0; p < 2; p++) {                                              \
        int i = tid + p * 256;                                                 \
        int row = i >> 3, c = i & 7;                                           \
        uint32_t off = (uint32_t)(row * AST + c * 16);                         \
        const int so = ((kb) + row) * HD + c * 8;                              \
        cp16(_bs + off,          Khg + so);                                    \
        cp16(_bs + KT_B + off,   Klg + so);                                    \
        cp16(_bs + 2*KT_B + off, Vhg + so);                                    \
        cp16(_bs + 3*KT_B + off, Vlg + so);                                    \
    }                                                                          \
} while (0)

    int kt0 = (q0 > SWIN) ? ((q0 - SWIN) >> 6) : 0;
    int ktE = 2 * qt + 1;                        // last tile: covers q0+127
    LOADKV(0, kt0 * 64);
    CP_COMMIT();

    uint32_t qh[4][4], ql[4][4];        // A frags, 4 k16 chunks
    float O[8][4];
    #pragma unroll
    for (int j = 0; j < 8; j++)
        #pragma unroll
        for (int e = 0; e < 4; e++) O[j][e] = 0.f;
    float m0 = -1e30f, m1 = -1e30f, l0 = 0.f, l1 = 0.f;

    int r0g = q0 + warp * 16 + (lane >> 2);       // global q rows for this thread
    int r1g = r0g + 8;

    for (int kt = kt0; kt <= ktE; kt++) {
        int st = (kt - kt0) & 1;
        if (kt + 1 <= ktE) LOADKV(st ^ 1, (kt + 1) * 64);
        CP_COMMIT();
        CP_WAIT1();
        __syncthreads();

        if (kt == kt0) {
            uint32_t qa = sb + (warp * 16 + (lane & 15)) * AST + (lane >> 4) * 16;
            #pragma unroll
            for (int kc = 0; kc < 4; kc++) {
                ldm4(qh[kc], qa + kc * 32);
                ldm4(ql[kc], qa + QT_B + kc * 32);
            }
        }

        uint32_t bs = sb + 2*QT_B + st * 4*KT_B;
        int kb = kt * 64;

        // ---- scores = Qh.Kh + Ql.Kh + Qh.Kl
        float sf[8][4];
        #pragma unroll
        for (int j = 0; j < 8; j++)
            #pragma unroll
            for (int e = 0; e < 4; e++) sf[j][e] = 0.f;

        uint32_t kaH = bs + (lane & 15) * AST + (lane >> 4) * 16;
        uint32_t kaL = kaH + KT_B;
        #pragma unroll
        for (int kc = 0; kc < 4; kc++) {
            uint32_t bh[4][4], bl[4][4];
            #pragma unroll
            for (int g = 0; g < 4; g++) {
                ldm4(bh[g], kaH + g * (16*AST) + kc * 32);
                ldm4(bl[g], kaL + g * (16*AST) + kc * 32);
            }
            #pragma unroll
            for (int g = 0; g < 4; g++) {
                mma_bf16(sf[2*g],   qh[kc], bh[g][0], bh[g][2]);
                mma_bf16(sf[2*g+1], qh[kc], bh[g][1], bh[g][3]);
                mma_bf16(sf[2*g],   ql[kc], bh[g][0], bh[g][2]);
                mma_bf16(sf[2*g+1], ql[kc], bh[g][1], bh[g][3]);
                mma_bf16(sf[2*g],   qh[kc], bl[g][0], bl[g][2]);
                mma_bf16(sf[2*g+1], qh[kc], bl[g][1], bl[g][3]);
            }
        }

        // ---- mask + online softmax (rows r0g, r1g)
        int c0 = kb + 2 * (lane & 3);
        float mx0 = -1e30f, mx1 = -1e30f;
        #pragma unroll
        for (int j = 0; j < 8; j++) {
            int k = c0 + 8 * j;
            sf[j][0] = ((unsigned)(r0g - k)     <= SWIN) ? sf[j][0] : -1e30f;
            sf[j][1] = ((unsigned)(r0g - k - 1) <= SWIN) ? sf[j][1] : -1e30f;
            sf[j][2] = ((unsigned)(r1g - k)     <= SWIN) ? sf[j][2] : -1e30f;
            sf[j][3] = ((unsigned)(r1g - k - 1) <= SWIN) ? sf[j][3] : -1e30f;
            mx0 = fmaxf(mx0, fmaxf(sf[j][0], sf[j][1]));
            mx1 = fmaxf(mx1, fmaxf(sf[j][2], sf[j][3]));
        }
        #pragma unroll
        for (int off = 1; off <= 2; off <<= 1) {
            mx0 = fmaxf(mx0, __shfl_xor_sync(0xffffffffu, mx0, off));
            mx1 = fmaxf(mx1, __shfl_xor_sync(0xffffffffu, mx1, off));
        }
        float mn0 = fmaxf(m0, mx0), mn1 = fmaxf(m1, mx1);
        float a0 = __expf(m0 - mn0), a1 = __expf(m1 - mn1);
        m0 = mn0; m1 = mn1;
        float s0 = 0.f, s1 = 0.f;
        #pragma unroll
        for (int j = 0; j < 8; j++) {
            sf[j][0] = __expf(sf[j][0] - mn0);
            sf[j][1] = __expf(sf[j][1] - mn0);
            sf[j][2] = __expf(sf[j][2] - mn1);
            sf[j][3] = __expf(sf[j][3] - mn1);
            s0 += sf[j][0] + sf[j][1];
            s1 += sf[j][2] + sf[j][3];
        }
        #pragma unroll
        for (int off = 1; off <= 2; off <<= 1) {
            s0 += __shfl_xor_sync(0xffffffffu, s0, off);
            s1 += __shfl_xor_sync(0xffffffffu, s1, off);
        }
        l0 = l0 * a0 + s0;
        l1 = l1 * a1 + s1;
        #pragma unroll
        for (int j = 0; j < 8; j++) {
            O[j][0] *= a0; O[j][1] *= a0; O[j][2] *= a1; O[j][3] *= a1;
        }

        // ---- pack P to bf16 hi/lo A-frags (C->A layout identity)
        uint32_t pah[4][4], pal[4][4];
        #pragma unroll
        for (int kc = 0; kc < 4; kc++) {
            #pragma unroll
            for (int half = 0; half < 2; half++) {
                int j = 2 * kc + half;
                #pragma unroll
                for (int rr = 0; rr < 2; rr++) {
                    float x = sf[j][2*rr], yv = sf[j][2*rr + 1];
                    __nv_bfloat16 hx = __float2bfloat16(x), hy = __float2bfloat16(yv);
                    __nv_bfloat16 lx = __float2bfloat16(x - __bfloat162float(hx));
                    __nv_bfloat16 ly = __float2bfloat16(yv - __bfloat162float(hy));
                    __nv_bfloat162 hh = __halves2bfloat162(hx, hy);
                    __nv_bfloat162 ll = __halves2bfloat162(lx, ly);
                    pah[kc][2*half + rr] = *(uint32_t*)&hh;
                    pal[kc][2*half + rr] = *(uint32_t*)&ll;
                }
            }
        }

        // ---- O += Ph.Vh + Pl.Vh + Ph.Vl   (V via ldmatrix.trans)
        uint32_t vaH = bs + 2*KT_B + (lane & 15) * AST + (lane >> 4) * 16;
        uint32_t vaL = vaH + KT_B;
        #pragma unroll
        for (int kc = 0; kc < 4; kc++) {
            #pragma unroll
            for (int dj = 0; dj < 4; dj++) {
                uint32_t vh[4], vl[4];
                ldm4t(vh, vaH + kc * (16*AST) + dj * 32);
                ldm4t(vl, vaL + kc * (16*AST) + dj * 32);
                mma_bf16(O[2*dj],   pah[kc], vh[0], vh[1]);
                mma_bf16(O[2*dj+1], pah[kc], vh[2], vh[3]);
                mma_bf16(O[2*dj],   pal[kc], vh[0], vh[1]);
                mma_bf16(O[2*dj+1], pal[kc], vh[2], vh[3]);
                mma_bf16(O[2*dj],   pah[kc], vl[0], vl[1]);
                mma_bf16(O[2*dj+1], pah[kc], vl[2], vl[3]);
            }
        }
        __syncthreads();
    }

    // ---- epilogue: write bf16 hi/lo split directly (feeds out-proj GEMM)
    float il0 = 1.0f / l0, il1 = 1.0f / l1;
    int dlo = 2 * (lane & 3);
    size_t base0 = ((size_t)(b * SEQ + r0g)) * HIDN + h * HD + dlo;
    size_t base1 = ((size_t)(b * SEQ + r1g)) * HIDN + h * HD + dlo;
    #pragma unroll
    for (int j = 0; j < 8; j++) {
        store_split(g_Ah, g_Al, base0 + 8*j, O[j][0] * il0, O[j][1] * il0);
        store_split(g_Ah, g_Al, base1 + 8*j, O[j][2] * il1, O[j][3] * il1);
    }
}

// ---------------- launch ---------------------------------------------------
extern "C" void kernel_launch(void* const* d_in, const int* in_sizes, int n_in,
                              void* d_out, int out_size)
{
    const float* X  = (const float*)d_in[0];
    const float* Wq = (const float*)d_in[2];
    const float* Wk = (const float*)d_in[3];
    const float* Wv = (const float*)d_in[4];
    const float* Wo = (const float*)d_in[5];
    float* out = (float*)d_out;

    cudaFuncSetAttribute(gemm_mma, cudaFuncAttributeMaxDynamicSharedMemorySize,
                         GSMEM_BYTES);
    cudaFuncSetAttribute(attn_mma, cudaFuncAttributeMaxDynamicSharedMemorySize,
                         ATTN_SMEM);

    const int NX4 = MTOT * HIDN / 4;     // 1,048,576
    const int NW4 = HIDN * HIDN / 4;     // 65,536

    // Launch order tuned so the ncu window (-s 5 -c 1, incl. 1 harness launch)
    // lands on the QKV GEMM next profile.
    rope_tab<<<SEQ, 32>>>();                                       // 0
    cvt_in<<<(NX4 + 255) / 256, 256>>>(X, NX4, 1.0f, 0);           // 1
    cvt_w<<<dim3(NW4 / 256, 3), 256>>>(Wq, Wk, Wv);                // 2
    cvt_in<<<(NW4 + 255) / 256, 256>>>(Wo, NW4, 1.0f, 2);          // 3
    gemm_mma<<<dim3(MTOT / 128, 12), 256, GSMEM_BYTES>>>(nullptr, 0);   // 4
    attn_mma<<<dim3(SEQ / 128, NH, BATCH), 256, ATTN_SMEM>>>();         // 5
    gemm_mma<<<dim3(MTOT / 128, HIDN / 128), 256, GSMEM_BYTES>>>(out, 1); // 6
}

// round 6
// speedup vs baseline: 1.1231x; 1.1231x over previous
#include <cuda_runtime.h>
#include <cuda_bf16.h>
#include <math.h>
#include <stdint.h>

#define BATCH 4
#define SEQ   2048
#define HIDN  512
#define NH    8
#define HD    64
#define SWIN  250
#define MTOT  (BATCH*SEQ)            // 8192
#define MATSZ (BATCH*NH*SEQ*HD)      // 4.19M elements per Q/K/V matrix

// ---------------- device-global scratch ------------------------------------
__device__ __nv_bfloat16 g_Xh[MTOT*HIDN], g_Xl[MTOT*HIDN];
__device__ __nv_bfloat16 g_Wh[3*HIDN*HIDN], g_Wl[3*HIDN*HIDN];  // Wq(.125)|Wk|Wv
__device__ __nv_bfloat16 g_Ah[MTOT*HIDN], g_Al[MTOT*HIDN];      // attn out, split
__device__ __nv_bfloat16 g_Woh[HIDN*HIDN], g_Wol[HIDN*HIDN];
__device__ __nv_bfloat16 g_Qh[MATSZ], g_Ql[MATSZ];   // RoPE'd, prescaled 1/8
__device__ __nv_bfloat16 g_Kh[MATSZ], g_Kl[MATSZ];   // RoPE'd
__device__ __nv_bfloat16 g_Vh[MATSZ], g_Vl[MATSZ];
__device__ float2 g_rope[SEQ*32];              // cos,sin per (pos, freq)

// ---------------- PTX helpers ----------------------------------------------
__device__ __forceinline__ uint32_t smem_u32(const void* p) {
    uint32_t a;
    asm("{ .reg .u64 t; cvta.to.shared.u64 t, %1; cvt.u32.u64 %0, t; }"
        : "=r"(a) : "l"(p));
    return a;
}
__device__ __forceinline__ void cp16(uint32_t d, const void* s) {
    asm volatile("cp.async.cg.shared.global [%0], [%1], 16;"
                 :: "r"(d), "l"(__cvta_generic_to_global(s)) : "memory");
}
#define CP_COMMIT() asm volatile("cp.async.commit_group;" ::: "memory")
#define CP_WAIT1()  asm volatile("cp.async.wait_group 1;" ::: "memory")

__device__ __forceinline__ void ldm4(uint32_t* r, uint32_t addr) {
    asm volatile("ldmatrix.sync.aligned.m8n8.x4.shared.b16 {%0,%1,%2,%3}, [%4];"
        : "=r"(r[0]), "=r"(r[1]), "=r"(r[2]), "=r"(r[3]) : "r"(addr));
}
__device__ __forceinline__ void ldm4t(uint32_t* r, uint32_t addr) {
    asm volatile("ldmatrix.sync.aligned.m8n8.x4.trans.shared.b16 {%0,%1,%2,%3}, [%4];"
        : "=r"(r[0]), "=r"(r[1]), "=r"(r[2]), "=r"(r[3]) : "r"(addr));
}
__device__ __forceinline__ void mma_bf16(float* d, const uint32_t* a,
                                         uint32_t b0, uint32_t b1) {
    asm volatile("mma.sync.aligned.m16n8k16.row.col.f32.bf16.bf16.f32 "
        "{%0,%1,%2,%3}, {%4,%5,%6,%7}, {%8,%9}, {%0,%1,%2,%3};"
        : "+f"(d[0]), "+f"(d[1]), "+f"(d[2]), "+f"(d[3])
        : "r"(a[0]), "r"(a[1]), "r"(a[2]), "r"(a[3]), "r"(b0), "r"(b1));
}

__device__ __forceinline__ void store_split(__nv_bfloat16* hp, __nv_bfloat16* lp,
                                            size_t idx, float x, float y) {
    __nv_bfloat16 hx = __float2bfloat16(x), hy = __float2bfloat16(y);
    __nv_bfloat16 lx = __float2bfloat16(x - __bfloat162float(hx));
    __nv_bfloat16 ly = __float2bfloat16(y - __bfloat162float(hy));
    *(__nv_bfloat162*)(hp + idx) = __halves2bfloat162(hx, hy);
    *(__nv_bfloat162*)(lp + idx) = __halves2bfloat162(lx, ly);
}

// ---------------- conversion kernels ---------------------------------------
// which: 0 = X -> g_Xh/g_Xl, 2 = Wo -> g_Woh/g_Wol
__global__ void cvt_in(const float* __restrict__ s, int n4, float scale, int which)
{
    int i = blockIdx.x * 256 + threadIdx.x;
    if (i >= n4) return;
    __nv_bfloat16 *hp, *lp;
    if (which == 0) { hp = g_Xh;  lp = g_Xl;  }
    else            { hp = g_Woh; lp = g_Wol; }
    float4 v = ((const float4*)s)[i];
    float x[4] = { v.x * scale, v.y * scale, v.z * scale, v.w * scale };
    __nv_bfloat16 h[4], l[4];
    #pragma unroll
    for (int j = 0; j < 4; j++) {
        h[j] = __float2bfloat16(x[j]);
        l[j] = __float2bfloat16(x[j] - __bfloat162float(h[j]));
    }
    ((__nv_bfloat162*)hp)[2*i]   = __halves2bfloat162(h[0], h[1]);
    ((__nv_bfloat162*)hp)[2*i+1] = __halves2bfloat162(h[2], h[3]);
    ((__nv_bfloat162*)lp)[2*i]   = __halves2bfloat162(l[0], l[1]);
    ((__nv_bfloat162*)lp)[2*i+1] = __halves2bfloat162(l[2], l[3]);
}

// Wq/Wk/Wv in one launch: blockIdx.y picks the matrix
__global__ void cvt_w(const float* __restrict__ Wq, const float* __restrict__ Wk,
                      const float* __restrict__ Wv)
{
    int y = blockIdx.y;
    const float* s = (y == 0) ? Wq : (y == 1) ? Wk : Wv;
    float scale = (y == 0) ? 0.125f : 1.0f;
    __nv_bfloat16* hp = g_Wh + (size_t)y * HIDN * HIDN;
    __nv_bfloat16* lp = g_Wl + (size_t)y * HIDN * HIDN;
    int i = blockIdx.x * 256 + threadIdx.x;          // n4 = 65536
    float4 v = ((const float4*)s)[i];
    float x[4] = { v.x * scale, v.y * scale, v.z * scale, v.w * scale };
    __nv_bfloat16 h[4], l[4];
    #pragma unroll
    for (int j = 0; j < 4; j++) {
        h[j] = __float2bfloat16(x[j]);
        l[j] = __float2bfloat16(x[j] - __bfloat162float(h[j]));
    }
    ((__nv_bfloat162*)hp)[2*i]   = __halves2bfloat162(h[0], h[1]);
    ((__nv_bfloat162*)hp)[2*i+1] = __halves2bfloat162(h[2], h[3]);
    ((__nv_bfloat162*)lp)[2*i]   = __halves2bfloat162(l[0], l[1]);
    ((__nv_bfloat162*)lp)[2*i+1] = __halves2bfloat162(l[2], l[3]);
}

__global__ void rope_tab()
{
    int pos = blockIdx.x, j = threadIdx.x;           // 2048 x 32
    double li = 9.210340371976184 / 32.0;            // ln(10000)/32
    float invf = (float)exp(-(double)j * li);
    float sn, cs;
    sincosf((float)pos * invf, &sn, &cs);
    g_rope[pos * 32 + j] = make_float2(cs, sn);
}

// ---------------- mma.sync GEMM, bf16 3-pass split -------------------------
// C[m,n] = sum_k A[m,k]*B[n,k];  tiles 128x128, K-chunk 32, 8 warps (4m x 2n)
// 2 CTAs/SM (smem 80KB x2 fits 228KB) hides sync/wait exposure.
#define TILE_B   10240
#define STAGE_B  40960
#define GSMEM_BYTES (2*STAGE_B)

__global__ __launch_bounds__(256, 2) void gemm_mma(float* __restrict__ outp, int mode)
{
    extern __shared__ char smem[];
    uint32_t sb = smem_u32(smem);
    int tid = threadIdx.x, lane = tid & 31, warp = tid >> 5;
    int mw = warp & 3, nw = warp >> 2;
    int m0 = blockIdx.x * 128;
    int y  = blockIdx.y;
    int n0g = y * 128;

    const __nv_bfloat16 *Agh, *Agl, *Bgh, *Bgl;
    if (mode == 0) { Agh = g_Xh; Agl = g_Xl; Bgh = g_Wh;  Bgl = g_Wl;  }
    else           { Agh = g_Ah; Agl = g_Al; Bgh = g_Woh; Bgl = g_Wol; }

    int lrow = tid >> 2, lq = tid & 3;
    const __nv_bfloat16* pAh = Agh + (size_t)(m0 + lrow) * HIDN + lq * 8;
    const __nv_bfloat16* pAl = Agl + (size_t)(m0 + lrow) * HIDN + lq * 8;
    const __nv_bfloat16* pBh = Bgh + (size_t)(n0g + lrow) * HIDN + lq * 8;
    const __nv_bfloat16* pBl = Bgl + (size_t)(n0g + lrow) * HIDN + lq * 8;
    uint32_t sdst = sb + lrow * 80 + lq * 16;

#define LDST(st, c) do {                                                       \
    int _k = (c) * 32;                                                         \
    uint32_t _d = sdst + (st) * STAGE_B;                                       \
    cp16(_d,                     pAh + _k); cp16(_d + 64*80,             pAh + _k + 64*HIDN); \
    cp16(_d + TILE_B,            pAl + _k); cp16(_d + TILE_B + 64*80,    pAl + _k + 64*HIDN); \
    cp16(_d + 2*TILE_B,          pBh + _k); cp16(_d + 2*TILE_B + 64*80,  pBh + _k + 64*HIDN); \
    cp16(_d + 3*TILE_B,          pBl + _k); cp16(_d + 3*TILE_B + 64*80,  pBl + _k + 64*HIDN); \
} while (0)

    float acc[2][8][4];
    #pragma unroll
    for (int a = 0; a < 2; a++)
        #pragma unroll
        for (int bq = 0; bq < 8; bq++)
            #pragma unroll
            for (int c = 0; c < 4; c++) acc[a][bq][c] = 0.f;

    uint32_t aaddr0 = sb + (mw * 32 + (lane & 15)) * 80 + (lane >> 4) * 16;
    uint32_t baddr0 = sb + 2 * TILE_B + (nw * 64 + (lane & 15)) * 80 + (lane >> 4) * 16;

    LDST(0, 0);
    CP_COMMIT();

    for (int c = 0; c < 16; c++) {
        if (c + 1 < 16) LDST((c + 1) & 1, c + 1);
        CP_COMMIT();
        CP_WAIT1();
        __syncthreads();
        uint32_t sa = aaddr0 + (c & 1) * STAGE_B;
        uint32_t sbb = baddr0 + (c & 1) * STAGE_B;
        #pragma unroll
        for (int ks = 0; ks < 2; ks++) {
            uint32_t ka = sa + ks * 32, kb = sbb + ks * 32;
            uint32_t ah[2][4], al[2][4];
            ldm4(ah[0], ka);          ldm4(ah[1], ka + 1280);
            ldm4(al[0], ka + TILE_B); ldm4(al[1], ka + TILE_B + 1280);
            // per-j B frags keep register pressure under the 128-reg cap
            #pragma unroll
            for (int j = 0; j < 4; j++) {
                uint32_t bh[4], bl[4];
                ldm4(bh, kb + j * 1280);
                ldm4(bl, kb + TILE_B + j * 1280);
                #pragma unroll
                for (int mi = 0; mi < 2; mi++) {
                    mma_bf16(acc[mi][2*j],   ah[mi], bh[0], bh[2]);
                    mma_bf16(acc[mi][2*j+1], ah[mi], bh[1], bh[3]);
                    mma_bf16(acc[mi][2*j],   al[mi], bh[0], bh[2]);
                    mma_bf16(acc[mi][2*j+1], al[mi], bh[1], bh[3]);
                    mma_bf16(acc[mi][2*j],   ah[mi], bl[0], bl[2]);
                    mma_bf16(acc[mi][2*j+1], ah[mi], bl[1], bl[3]);
                }
            }
        }
        __syncthreads();
    }

    if (mode == 0) {
        int mat = y >> 2;                       // 0=Q,1=K,2=V
        int h   = ((y & 3) << 1) + nw;          // head
        __nv_bfloat16 *hp, *lp;
        if (mat == 0)      { hp = g_Qh; lp = g_Ql; }
        else if (mat == 1) { hp = g_Kh; lp = g_Kl; }
        else               { hp = g_Vh; lp = g_Vl; }
        #pragma unroll
        for (int mi = 0; mi < 2; mi++)
            #pragma unroll
            for (int half = 0; half < 2; half++) {
                int m = m0 + mw * 32 + mi * 16 + (lane >> 2) + half * 8;
                int bb = m >> 11, spos = m & (SEQ - 1);
                size_t base = ((size_t)(bb * NH + h) * SEQ + spos) * HD;
                int dlo = 2 * (lane & 3);
                if (mat == 2) {
                    #pragma unroll
                    for (int p = 0; p < 8; p++)
                        store_split(hp, lp, base + p * 8 + dlo,
                                    acc[mi][p][2*half], acc[mi][p][2*half+1]);
                } else {
                    #pragma unroll
                    for (int p = 0; p < 4; p++) {
                        int d = p * 8 + dlo;
                        float4 t = *(const float4*)&g_rope[spos * 32 + d]; // cs0,sn0,cs1,sn1
                        float a0 = acc[mi][p][2*half],   a1 = acc[mi][p][2*half+1];
                        float b0 = acc[mi][p+4][2*half], b1 = acc[mi][p+4][2*half+1];
                        store_split(hp, lp, base + d,      a0*t.x - b0*t.y, a1*t.z - b1*t.w);
                        store_split(hp, lp, base + d + 32, b0*t.x + a0*t.y, b1*t.z + a1*t.w);
                    }
                }
            }
    } else {
        #pragma unroll
        for (int mi = 0; mi < 2; mi++)
            #pragma unroll
            for (int half = 0; half < 2; half++) {
                int m = m0 + mw * 32 + mi * 16 + (lane >> 2) + half * 8;
                float* dst = outp + (size_t)m * HIDN + n0g + nw * 64 + 2 * (lane & 3);
                #pragma unroll
                for (int p = 0; p < 8; p++)
                    *(float2*)&dst[p * 8] =
                        make_float2(acc[mi][p][2*half], acc[mi][p][2*half+1]);
            }
    }
}

// ---------------- flash attention via mma.sync bf16-split ------------------
// Block = 64 q rows, 4 warps (16 rows each), k-tile 64, 2-stage cp.async.
// smem rows padded to 144 B for conflict-free ldmatrix.
#define AST     144
#define KT_B    (64*AST)                        // 9216 per tile
#define ATTN_SMEM (2*KT_B + 2*4*KT_B)           // Qh,Ql + 2 stages x (Kh,Kl,Vh,Vl)

__global__ __launch_bounds__(128) void attn_mma()
{
    extern __shared__ char smem[];
    uint32_t sb = smem_u32(smem);
    int tid = threadIdx.x, lane = tid & 31, warp = tid >> 5;
    int qt = blockIdx.x, h = blockIdx.y, b = blockIdx.z;
    int q0 = qt * 64;
    size_t hoff = (size_t)(b * NH + h) * SEQ * HD;
    const __nv_bfloat16 *Qhg = g_Qh + hoff + (size_t)q0 * HD;
    const __nv_bfloat16 *Qlg = g_Ql + hoff + (size_t)q0 * HD;
    const __nv_bfloat16 *Khg = g_Kh + hoff, *Klg = g_Kl + hoff;
    const __nv_bfloat16 *Vhg = g_Vh + hoff, *Vlg = g_Vl + hoff;

    // prologue: Q tiles (hi, lo)
    #pragma unroll
    for (int p = 0; p < 4; p++) {
        int i = tid + p * 128;
        int row = i >> 3, c = i & 7;
        uint32_t off = (uint32_t)(row * AST + c * 16);
        const int so = row * HD + c * 8;
        cp16(sb + off,        Qhg + so);
        cp16(sb + KT_B + off, Qlg + so);
    }

#define LOADKV(st, kb) do {                                                    \
    uint32_t _bs = sb + 2*KT_B + (st) * 4*KT_B;                                \
    _Pragma("unroll")                                                          \
    for (int p = 0; p < 4; p++) {                                              \
        int i = tid + p * 128;                                                 \
        int row = i >> 3, c = i & 7;                                           \
        uint32_t off = (uint32_t)(row * AST + c * 16);                         \
        const int so = ((kb) + row) * HD + c * 8;                              \
        cp16(_bs + off,          Khg + so);                                    \
        cp16(_bs + KT_B + off,   Klg + so);                                    \
        cp16(_bs + 2*KT_B + off, Vhg + so);                                    \
        cp16(_bs + 3*KT_B + off, Vlg + so);                                    \
    }                                                                          \
} while (0)

    int kt0 = (q0 > SWIN) ? ((q0 - SWIN) >> 6) : 0;
    LOADKV(0, kt0 * 64);
    CP_COMMIT();

    uint32_t qh[4][4], ql[4][4];        // A frags, 4 k16 chunks
    float O[8][4];
    #pragma unroll
    for (int j = 0; j < 8; j++)
        #pragma unroll
        for (int e = 0; e < 4; e++) O[j][e] = 0.f;
    float m0 = -1e30f, m1 = -1e30f, l0 = 0.f, l1 = 0.f;

    int r0g = q0 + warp * 16 + (lane >> 2);       // global q rows for this thread
    int r1g = r0g + 8;

    for (int kt = kt0; kt <= qt; kt++) {
        int st = (kt - kt0) & 1;
        if (kt + 1 <= qt) LOADKV(st ^ 1, (kt + 1) * 64);
        CP_COMMIT();
        CP_WAIT1();
        __syncthreads();

        if (kt == kt0) {
            uint32_t qa = sb + (warp * 16 + (lane & 15)) * AST + (lane >> 4) * 16;
            #pragma unroll
            for (int kc = 0; kc < 4; kc++) {
                ldm4(qh[kc], qa + kc * 32);
                ldm4(ql[kc], qa + KT_B + kc * 32);
            }
        }

        uint32_t bs = sb + 2*KT_B + st * 4*KT_B;
        int kb = kt * 64;

        // ---- scores = Qh.Kh + Ql.Kh + Qh.Kl
        float sf[8][4];
        #pragma unroll
        for (int j = 0; j < 8; j++)
            #pragma unroll
            for (int e = 0; e < 4; e++) sf[j][e] = 0.f;

        uint32_t kaH = bs + (lane & 15) * AST + (lane >> 4) * 16;
        uint32_t kaL = kaH + KT_B;
        #pragma unroll
        for (int kc = 0; kc < 4; kc++) {
            #pragma unroll
            for (int g = 0; g < 4; g++) {
                uint32_t bh[4], bl[4];
                ldm4(bh, kaH + g * (16*AST) + kc * 32);
                ldm4(bl, kaL + g * (16*AST) + kc * 32);
                mma_bf16(sf[2*g],   qh[kc], bh[0], bh[2]);
                mma_bf16(sf[2*g+1], qh[kc], bh[1], bh[3]);
                mma_bf16(sf[2*g],   ql[kc], bh[0], bh[2]);
                mma_bf16(sf[2*g+1], ql[kc], bh[1], bh[3]);
                mma_bf16(sf[2*g],   qh[kc], bl[0], bl[2]);
                mma_bf16(sf[2*g+1], qh[kc], bl[1], bl[3]);
            }
        }

        // ---- mask + online softmax (rows r0g, r1g)
        int c0 = kb + 2 * (lane & 3);
        float mx0 = -1e30f, mx1 = -1e30f;
        #pragma unroll
        for (int j = 0; j < 8; j++) {
            int k = c0 + 8 * j;
            sf[j][0] = ((unsigned)(r0g - k)     <= SWIN) ? sf[j][0] : -1e30f;
            sf[j][1] = ((unsigned)(r0g - k - 1) <= SWIN) ? sf[j][1] : -1e30f;
            sf[j][2] = ((unsigned)(r1g - k)     <= SWIN) ? sf[j][2] : -1e30f;
            sf[j][3] = ((unsigned)(r1g - k - 1) <= SWIN) ? sf[j][3] : -1e30f;
            mx0 = fmaxf(mx0, fmaxf(sf[j][0], sf[j][1]));
            mx1 = fmaxf(mx1, fmaxf(sf[j][2], sf[j][3]));
        }
        #pragma unroll
        for (int off = 1; off <= 2; off <<= 1) {
            mx0 = fmaxf(mx0, __shfl_xor_sync(0xffffffffu, mx0, off));
            mx1 = fmaxf(mx1, __shfl_xor_sync(0xffffffffu, mx1, off));
        }
        float mn0 = fmaxf(m0, mx0), mn1 = fmaxf(m1, mx1);
        float a0 = __expf(m0 - mn0), a1 = __expf(m1 - mn1);
        m0 = mn0; m1 = mn1;
        float s0 = 0.f, s1 = 0.f;
        #pragma unroll
        for (int j = 0; j < 8; j++) {
            sf[j][0] = __expf(sf[j][0] - mn0);
            sf[j][1] = __expf(sf[j][1] - mn0);
            sf[j][2] = __expf(sf[j][2] - mn1);
            sf[j][3] = __expf(sf[j][3] - mn1);
            s0 += sf[j][0] + sf[j][1];
            s1 += sf[j][2] + sf[j][3];
        }
        #pragma unroll
        for (int off = 1; off <= 2; off <<= 1) {
            s0 += __shfl_xor_sync(0xffffffffu, s0, off);
            s1 += __shfl_xor_sync(0xffffffffu, s1, off);
        }
        l0 = l0 * a0 + s0;
        l1 = l1 * a1 + s1;
        #pragma unroll
        for (int j = 0; j < 8; j++) {
            O[j][0] *= a0; O[j][1] *= a0; O[j][2] *= a1; O[j][3] *= a1;
        }

        // ---- pack P to bf16 hi/lo A-frags (C->A layout identity)
        uint32_t pah[4][4], pal[4][4];
        #pragma unroll
        for (int kc = 0; kc < 4; kc++) {
            #pragma unroll
            for (int half = 0; half < 2; half++) {
                int j = 2 * kc + half;
                #pragma unroll
                for (int rr = 0; rr < 2; rr++) {
                    float x = sf[j][2*rr], yv = sf[j][2*rr + 1];
                    __nv_bfloat16 hx = __float2bfloat16(x), hy = __float2bfloat16(yv);
                    __nv_bfloat16 lx = __float2bfloat16(x - __bfloat162float(hx));
                    __nv_bfloat16 ly = __float2bfloat16(yv - __bfloat162float(hy));
                    __nv_bfloat162 hh = __halves2bfloat162(hx, hy);
                    __nv_bfloat162 ll = __halves2bfloat162(lx, ly);
                    pah[kc][2*half + rr] = *(uint32_t*)&hh;
                    pal[kc][2*half + rr] = *(uint32_t*)&ll;
                }
            }
        }

        // ---- O += Ph.Vh + Pl.Vh + Ph.Vl   (V via ldmatrix.trans)
        uint32_t vaH = bs + 2*KT_B + (lane & 15) * AST + (lane >> 4) * 16;
        uint32_t vaL = vaH + KT_B;
        #pragma unroll
        for (int kc = 0; kc < 4; kc++) {
            #pragma unroll
            for (int dj = 0; dj < 4; dj++) {
                uint32_t vh[4], vl[4];
                ldm4t(vh, vaH + kc * (16*AST) + dj * 32);
                ldm4t(vl, vaL + kc * (16*AST) + dj * 32);
                mma_bf16(O[2*dj],   pah[kc], vh[0], vh[1]);
                mma_bf16(O[2*dj+1], pah[kc], vh[2], vh[3]);
                mma_bf16(O[2*dj],   pal[kc], vh[0], vh[1]);
                mma_bf16(O[2*dj+1], pal[kc], vh[2], vh[3]);
                mma_bf16(O[2*dj],   pah[kc], vl[0], vl[1]);
                mma_bf16(O[2*dj+1], pah[kc], vl[2], vl[3]);
            }
        }
        __syncthreads();
    }

    // ---- epilogue: write bf16 hi/lo split directly (feeds out-proj GEMM)
    float il0 = 1.0f / l0, il1 = 1.0f / l1;
    int dlo = 2 * (lane & 3);
    size_t base0 = ((size_t)(b * SEQ + r0g)) * HIDN + h * HD + dlo;
    size_t base1 = ((size_t)(b * SEQ + r1g)) * HIDN + h * HD + dlo;
    #pragma unroll
    for (int j = 0; j < 8; j++) {
        store_split(g_Ah, g_Al, base0 + 8*j, O[j][0] * il0, O[j][1] * il0);
        store_split(g_Ah, g_Al, base1 + 8*j, O[j][2] * il1, O[j][3] * il1);
    }
}

// ---------------- launch ---------------------------------------------------
extern "C" void kernel_launch(void* const* d_in, const int* in_sizes, int n_in,
                              void* d_out, int out_size)
{
    const float* X  = (const float*)d_in[0];
    const float* Wq = (const float*)d_in[2];
    const float* Wk = (const float*)d_in[3];
    const float* Wv = (const float*)d_in[4];
    const float* Wo = (const float*)d_in[5];
    float* out = (float*)d_out;

    cudaFuncSetAttribute(gemm_mma, cudaFuncAttributeMaxDynamicSharedMemorySize,
                         GSMEM_BYTES);
    cudaFuncSetAttribute(attn_mma, cudaFuncAttributeMaxDynamicSharedMemorySize,
                         ATTN_SMEM);

    const int NX4 = MTOT * HIDN / 4;     // 1,048,576
    const int NW4 = HIDN * HIDN / 4;     // 65,536

    // ncu window lands on our launch index 3 -> put the QKV GEMM there.
    rope_tab<<<SEQ, 32>>>();                                       // 0
    cvt_in<<<(NX4 + 255) / 256, 256>>>(X, NX4, 1.0f, 0);           // 1
    cvt_w<<<dim3(NW4 / 256, 3), 256>>>(Wq, Wk, Wv);                // 2
    gemm_mma<<<dim3(MTOT / 128, 12), 256, GSMEM_BYTES>>>(nullptr, 0);   // 3
    attn_mma<<<dim3(SEQ / 64, NH, BATCH), 128, ATTN_SMEM>>>();          // 4
    cvt_in<<<(NW4 + 255) / 256, 256>>>(Wo, NW4, 1.0f, 2);               // 5
    gemm_mma<<<dim3(MTOT / 128, HIDN / 128), 256, GSMEM_BYTES>>>(out, 1); // 6
}